// round 10
// baseline (speedup 1.0000x reference)
#include <cuda_runtime.h>
#include <cstddef>

// Problem shape
#define BATCH 4096
#define FN    1024
#define RC    19
#define RD    1024
#define FLAT  (FN * RC)            // 19456 floats per conv batch row

#define NBLKS    512               // 4096 warps, warp-per-batch
#define W_BLOCKS 128               // blocks 0..127 compute W (8 f's each)

__device__ float    g_W[FLAT];     // W[f][r] flat, matches conv's [f*19+r]
__device__ unsigned g_done;        // W-block completion counter (zeroed per launch)

__device__ __forceinline__ unsigned acq_load(const unsigned* p) {
    unsigned v;
    asm volatile("ld.acquire.gpu.global.u32 %0, [%1];" : "=r"(v) : "l"(p));
    return v;
}

// ---------------------------------------------------------------------------
// Fused kernel.
// Phase W (blocks 0..127): warp wid computes f = bid*8 + wid.
//   U row held in 32 regs; 19 R-row dots via __ldg (block's 8 warps share R
//   rows through L1 -> ~10 MB L2 total). Release: fence + atomicAdd(g_done).
// Phase spin (all other warps, and W warps after their work): acquire-spin on
//   g_done while issuing prefetch.global.L2 on their OWN conv range — DRAM
//   streaming starts at t=0 and fully overlaps the W phase.
// Phase score (all 4096 warps): exact r2 hot path — 152 unit-stride float4
//   __ldcs loads paired with L1-resident W, rotating compile-time accumulator
//   slots, one shuffle butterfly, direct stores.
//   Residues: flat idx = i*128 + 4*lane + j, 128 % 19 = 14:
//     r = (14*i + 4*lane + j) mod 19, slot k = (14*i + j) mod 19.
// ---------------------------------------------------------------------------
__global__ __launch_bounds__(256, 4)
void fused_kernel(const float* __restrict__ conv,
                  const float* __restrict__ U,
                  const float* __restrict__ R,
                  float* __restrict__ out) {
    const int lane = threadIdx.x & 31;
    const int wid  = threadIdx.x >> 5;
    const int bid  = blockIdx.x;
    const int b    = bid * 8 + wid;          // this warp's batch

    const float4* c4 = reinterpret_cast<const float4*>(conv + (size_t)b * FLAT);

    // ---------------- Phase W ----------------
    if (bid < W_BLOCKS) {
        const int f = bid * 8 + wid;         // 0..1023
        const float4* u4 = reinterpret_cast<const float4*>(U + (size_t)f * RD);
        float4 u[8];
#pragma unroll
        for (int i = 0; i < 8; i++) u[i] = u4[lane + 32 * i];

        for (int r = 0; r < RC; r++) {
            const float4* r4 = reinterpret_cast<const float4*>(R + (size_t)r * RD);
            float s = 0.f;
#pragma unroll
            for (int i = 0; i < 8; i++) {
                float4 rv = __ldg(&r4[lane + 32 * i]);   // L1-shared across warps
                s += u[i].x * rv.x + u[i].y * rv.y + u[i].z * rv.z + u[i].w * rv.w;
            }
#pragma unroll
            for (int off = 16; off > 0; off >>= 1)
                s += __shfl_xor_sync(0xffffffffu, s, off);
            if (lane == 0) g_W[f * RC + r] = s;
        }
        __syncthreads();                      // all 8 warps' W rows written
        if (threadIdx.x == 0) {
            __threadfence();                  // release g_W stores
            atomicAdd(&g_done, 1u);
        }
    }

    // ---------------- Phase spin + L2 prefetch ----------------
    unsigned v;
    int pfi = 0;
    while ((v = acq_load(&g_done)) < (unsigned)W_BLOCKS) {
        if (pfi < 152) {
#pragma unroll
            for (int j = 0; j < 8; j++) {
                const float4* pa = c4 + (pfi + j) * 32 + lane;
                asm volatile("prefetch.global.L2 [%0];" :: "l"(pa));
            }
            pfi += 8;
        } else {
            __nanosleep(64);
        }
    }
    asm volatile("" ::: "memory");
    // Data dependency: (v - W_BLOCKS) == 0; pins conv/W reads after the spin.
    const float4* c4d = c4 + (v - (unsigned)W_BLOCKS);
    const float4* w4  = reinterpret_cast<const float4*>(g_W);

    // ---------------- Phase score ----------------
    float acc[RC];
#pragma unroll
    for (int k = 0; k < RC; k++) acc[k] = 0.f;

    for (int o = 0; o < 8; o++) {
        const int base = o * (19 * 32) + lane;
#pragma unroll
        for (int t = 0; t < 19; t++) {
            float4 cv = __ldcs(&c4d[base + t * 32]);   // streaming, read-once
            float4 wv = __ldg(&w4[base + t * 32]);     // L1-resident
            acc[(14 * t + 0) % RC] += cv.x * wv.x;
            acc[(14 * t + 1) % RC] += cv.y * wv.y;
            acc[(14 * t + 2) % RC] += cv.z * wv.z;
            acc[(14 * t + 3) % RC] += cv.w * wv.w;
        }
    }

    // Butterfly: lane l slot k holds r=(4l+k)%19; peer l+d has it at (k-4d)%19.
#pragma unroll
    for (int d = 16; d >= 1; d >>= 1) {
        float tmp[RC];
#pragma unroll
        for (int k = 0; k < RC; k++) {
            const int s = (k + 4 * RC - 4 * d) % RC;
            tmp[k] = __shfl_down_sync(0xffffffffu, acc[s], d);
        }
#pragma unroll
        for (int k = 0; k < RC; k++) acc[k] += tmp[k];
    }

    // Lane 0: slot k == relation k (r0 = 0). Direct stores, no atomics.
    if (lane == 0) {
        float* ob = out + (size_t)b * RC;
#pragma unroll
        for (int k = 0; k < RC; k++) ob[k] = acc[k];
    }
}

// ---------------------------------------------------------------------------
// Launch: one memset (flag) + one kernel. Graph-capturable, no allocations.
// ---------------------------------------------------------------------------
extern "C" void kernel_launch(void* const* d_in, const int* in_sizes, int n_in,
                              void* d_out, int out_size) {
    const float* conv = nullptr;
    const float* R    = nullptr;
    const float* U    = nullptr;
    for (int i = 0; i < n_in; i++) {
        long long n = in_sizes[i];
        if (n == (long long)BATCH * FN * RC)      conv = (const float*)d_in[i];
        else if (n == (long long)RC * RD)         R    = (const float*)d_in[i];
        else if (n == (long long)FN * RD)         U    = (const float*)d_in[i];
    }
    float* out = (float*)d_out;

    void* sym = nullptr;
    cudaGetSymbolAddress(&sym, g_done);
    cudaMemsetAsync(sym, 0, sizeof(unsigned));

    fused_kernel<<<NBLKS, 256>>>(conv, U, R, out);
}

// round 12
// speedup vs baseline: 1.2106x; 1.2106x over previous
#include <cuda_runtime.h>
#include <cstddef>

// Problem shape
#define BATCH 4096
#define FN    1024
#define RC    19
#define RD    1024
#define FLAT  (FN * RC)            // 19456 floats per conv batch row

#define NBLKS    512               // 4096 warps, warp-per-batch
#define W_BLOCKS 128               // blocks 0..127 compute W (8 f's each)

__device__ float    g_W[FLAT];     // W[f][r] flat, matches conv's [f*19+r]
__device__ unsigned g_done;        // W-block completion counter (zeroed per launch)

__device__ __forceinline__ unsigned acq_load(const unsigned* p) {
    unsigned v;
    asm volatile("ld.acquire.gpu.global.u32 %0, [%1];" : "=r"(v) : "l"(p));
    return v;
}

// ---------------------------------------------------------------------------
// Fused kernel.
//
// Phase W (blocks 0..127): warp wid computes f = bid*8 + wid. U row in 32
//   regs; 19 R-row dots via __ldg (8 warps share R rows through L1 ->
//   ~10 MB L2 total, ~2-3 us). Release: __syncthreads, then thread 0:
//   __threadfence + atomicAdd(g_done).
//
// Phase spin (everyone): pure acquire-load + __nanosleep. No prefetch, no
//   extra DRAM traffic, negligible issue pressure. Deadlock-free: all 512
//   blocks are resident in wave 1 (4 blocks/SM x >=148 SMs), so every
//   W-producer block runs concurrently with the spinners.
//
// Phase score (all 4096 warps): the empirically-best r2 hot path — 152
//   unit-stride float4 __ldcs loads paired with L1-resident W (__ldg),
//   rotating compile-time accumulator slots, one shuffle butterfly, direct
//   stores. Residues: flat idx = i*128 + 4*lane + j, 128 % 19 = 14:
//     r = (14*i + 4*lane + j) mod 19, slot k = (14*i + j) mod 19.
// ---------------------------------------------------------------------------
__global__ __launch_bounds__(256, 4)
void fused_kernel(const float* __restrict__ conv,
                  const float* __restrict__ U,
                  const float* __restrict__ R,
                  float* __restrict__ out) {
    const int lane = threadIdx.x & 31;
    const int wid  = threadIdx.x >> 5;
    const int bid  = blockIdx.x;
    const int b    = bid * 8 + wid;          // this warp's batch

    // ---------------- Phase W ----------------
    if (bid < W_BLOCKS) {
        const int f = bid * 8 + wid;         // 0..1023
        const float4* u4 = reinterpret_cast<const float4*>(U + (size_t)f * RD);
        float4 u[8];
#pragma unroll
        for (int i = 0; i < 8; i++) u[i] = u4[lane + 32 * i];

        for (int r = 0; r < RC; r++) {
            const float4* r4 = reinterpret_cast<const float4*>(R + (size_t)r * RD);
            float s = 0.f;
#pragma unroll
            for (int i = 0; i < 8; i++) {
                float4 rv = __ldg(&r4[lane + 32 * i]);   // L1-shared across warps
                s += u[i].x * rv.x + u[i].y * rv.y + u[i].z * rv.z + u[i].w * rv.w;
            }
#pragma unroll
            for (int off = 16; off > 0; off >>= 1)
                s += __shfl_xor_sync(0xffffffffu, s, off);
            if (lane == 0) g_W[f * RC + r] = s;
        }
        __syncthreads();                      // all 8 warps' W rows written
        if (threadIdx.x == 0) {
            __threadfence();                  // release g_W stores
            atomicAdd(&g_done, 1u);
        }
    }

    // ---------------- Phase spin (quiet) ----------------
    unsigned v;
    while ((v = acq_load(&g_done)) < (unsigned)W_BLOCKS)
        __nanosleep(128);
    asm volatile("" ::: "memory");
    // Data dependency: (v - W_BLOCKS) == 0; pins conv/W reads after the spin.
    const float4* c4d = reinterpret_cast<const float4*>(conv + (size_t)b * FLAT)
                        + (v - (unsigned)W_BLOCKS);
    const float4* w4  = reinterpret_cast<const float4*>(g_W);

    // ---------------- Phase score ----------------
    float acc[RC];
#pragma unroll
    for (int k = 0; k < RC; k++) acc[k] = 0.f;

    for (int o = 0; o < 8; o++) {
        const int base = o * (19 * 32) + lane;
#pragma unroll
        for (int t = 0; t < 19; t++) {
            float4 cv = __ldcs(&c4d[base + t * 32]);   // streaming, read-once
            float4 wv = __ldg(&w4[base + t * 32]);     // L1-resident
            acc[(14 * t + 0) % RC] += cv.x * wv.x;
            acc[(14 * t + 1) % RC] += cv.y * wv.y;
            acc[(14 * t + 2) % RC] += cv.z * wv.z;
            acc[(14 * t + 3) % RC] += cv.w * wv.w;
        }
    }

    // Butterfly: lane l slot k holds r=(4l+k)%19; peer l+d has it at (k-4d)%19.
#pragma unroll
    for (int d = 16; d >= 1; d >>= 1) {
        float tmp[RC];
#pragma unroll
        for (int k = 0; k < RC; k++) {
            const int s = (k + 4 * RC - 4 * d) % RC;
            tmp[k] = __shfl_down_sync(0xffffffffu, acc[s], d);
        }
#pragma unroll
        for (int k = 0; k < RC; k++) acc[k] += tmp[k];
    }

    // Lane 0: slot k == relation k (r0 = 0). Direct stores, no atomics.
    if (lane == 0) {
        float* ob = out + (size_t)b * RC;
#pragma unroll
        for (int k = 0; k < RC; k++) ob[k] = acc[k];
    }
}

// ---------------------------------------------------------------------------
// Launch: one 4-byte memset (flag) + one kernel. Graph-capturable.
// ---------------------------------------------------------------------------
extern "C" void kernel_launch(void* const* d_in, const int* in_sizes, int n_in,
                              void* d_out, int out_size) {
    const float* conv = nullptr;
    const float* R    = nullptr;
    const float* U    = nullptr;
    for (int i = 0; i < n_in; i++) {
        long long n = in_sizes[i];
        if (n == (long long)BATCH * FN * RC)      conv = (const float*)d_in[i];
        else if (n == (long long)RC * RD)         R    = (const float*)d_in[i];
        else if (n == (long long)FN * RD)         U    = (const float*)d_in[i];
    }
    float* out = (float*)d_out;

    void* sym = nullptr;
    cudaGetSymbolAddress(&sym, g_done);
    cudaMemsetAsync(sym, 0, sizeof(unsigned));

    fused_kernel<<<NBLKS, 256>>>(conv, U, R, out);
}

// round 14
// speedup vs baseline: 1.4676x; 1.2122x over previous
#include <cuda_runtime.h>
#include <cstddef>

// Problem shape
#define BATCH 4096
#define FN    1024
#define RC    19
#define RD    1024
#define FLAT  (FN * RC)            // 19456 floats per conv batch row

#define CW_SMEM_BYTES (5 * RD * 4) // 20 KB: up to 5 staged R rows

__device__ float g_W[FLAT];        // W[f][r] flat, matches conv's [f*19+r]

// ---------------------------------------------------------------------------
// Kernel 1: W = U @ R^T, split 4-ways along r for low per-block latency.
// 512 blocks x 256 threads. Block bid: fgrp = bid>>2 (8 f's), q = bid&3
// (r range: q*5 .. q*5+nr, nr = 5,5,5,4). Stage the nr R rows (<=20 KB) in
// smem; warp wid computes f = fgrp*8 + wid with its U row in registers.
// Per-block serial work ~4x smaller than the 128-block variant (~1 us).
// U is read by 4 blocks per f-group -> 16 MB of L2 traffic (irrelevant).
// ---------------------------------------------------------------------------
__global__ void compute_w_kernel(const float* __restrict__ U,
                                 const float* __restrict__ R) {
    extern __shared__ float sR[];            // nr * 1024 floats
    const int tid  = threadIdx.x;
    const int lane = tid & 31;
    const int wid  = tid >> 5;

    const int q    = blockIdx.x & 3;
    const int fgrp = blockIdx.x >> 2;
    const int r0   = q * 5;
    const int nr   = (q < 3) ? 5 : 4;

    // Stage nr R rows: nr*256 float4 over 256 threads (coalesced).
    {
        float4* s4 = reinterpret_cast<float4*>(sR);
        const float4* g4 = reinterpret_cast<const float4*>(R + (size_t)r0 * RD);
        for (int k = tid; k < nr * 256; k += 256)
            s4[k] = g4[k];
    }
    __syncthreads();

    const int f = fgrp * 8 + wid;
    const float4* u4 = reinterpret_cast<const float4*>(U + (size_t)f * RD);
    float4 u[8];
#pragma unroll
    for (int i = 0; i < 8; i++) u[i] = u4[lane + 32 * i];

    for (int rr = 0; rr < nr; rr++) {
        const float4* r4 = reinterpret_cast<const float4*>(sR + (size_t)rr * RD);
        float s = 0.f;
#pragma unroll
        for (int i = 0; i < 8; i++) {
            float4 rv = r4[lane + 32 * i];
            s += u[i].x * rv.x + u[i].y * rv.y + u[i].z * rv.z + u[i].w * rv.w;
        }
#pragma unroll
        for (int off = 16; off > 0; off >>= 1)
            s += __shfl_xor_sync(0xffffffffu, s, off);
        if (lane == 0) g_W[f * RC + (r0 + rr)] = s;
    }
}

// ---------------------------------------------------------------------------
// Kernel 2: score[b][r] = sum_f conv[b][f][r] * W[f][r]
// EXACT r2 hot path (best measurement: 54.7 us, 74.4% DRAM):
// warp-per-batch b = blk*8 + wid, 152 unit-stride float4 __ldcs loads paired
// with L1-resident W, rotating compile-time accumulator slots, one shuffle
// butterfly, direct stores. Residues: flat idx = i*128 + 4*lane + j,
// 128 % 19 = 14: r = (14*i+4*lane+j) mod 19, slot k = (14*i+j) mod 19.
// ---------------------------------------------------------------------------
__global__ __launch_bounds__(256, 4)
void score_kernel(const float* __restrict__ conv, float* __restrict__ out) {
    const int lane = threadIdx.x & 31;
    const int b    = blockIdx.x * 8 + (threadIdx.x >> 5);   // warp-per-batch

    const float4* c4 = reinterpret_cast<const float4*>(conv + (size_t)b * FLAT);
    const float4* w4 = reinterpret_cast<const float4*>(g_W);

    float acc[RC];
#pragma unroll
    for (int k = 0; k < RC; k++) acc[k] = 0.f;

    // 152 warp-iterations = 8 outer x 19 inner (slot pattern period = 19)
    for (int o = 0; o < 8; o++) {
        const int base = o * (19 * 32) + lane;
#pragma unroll
        for (int t = 0; t < 19; t++) {
            float4 cv = __ldcs(&c4[base + t * 32]);   // streaming, read-once
            float4 wv = w4[base + t * 32];            // L1-resident
            acc[(14 * t + 0) % RC] += cv.x * wv.x;
            acc[(14 * t + 1) % RC] += cv.y * wv.y;
            acc[(14 * t + 2) % RC] += cv.z * wv.z;
            acc[(14 * t + 3) % RC] += cv.w * wv.w;
        }
    }

    // Butterfly: lane l slot k holds r=(4l+k)%19; peer l+d has it at (k-4d)%19.
#pragma unroll
    for (int d = 16; d >= 1; d >>= 1) {
        float tmp[RC];
#pragma unroll
        for (int k = 0; k < RC; k++) {
            const int s = (k + 4 * RC - 4 * d) % RC;
            tmp[k] = __shfl_down_sync(0xffffffffu, acc[s], d);
        }
#pragma unroll
        for (int k = 0; k < RC; k++) acc[k] += tmp[k];
    }

    // Lane 0: slot k == relation k (r0 = 0). Direct stores, no atomics.
    if (lane == 0) {
        float* ob = out + (size_t)b * RC;
#pragma unroll
        for (int k = 0; k < RC; k++) ob[k] = acc[k];
    }
}

// ---------------------------------------------------------------------------
// Launch: two kernels, same stream. Graph-capturable, no allocations.
// ---------------------------------------------------------------------------
extern "C" void kernel_launch(void* const* d_in, const int* in_sizes, int n_in,
                              void* d_out, int out_size) {
    const float* conv = nullptr;
    const float* R    = nullptr;
    const float* U    = nullptr;
    for (int i = 0; i < n_in; i++) {
        long long n = in_sizes[i];
        if (n == (long long)BATCH * FN * RC)      conv = (const float*)d_in[i];
        else if (n == (long long)RC * RD)         R    = (const float*)d_in[i];
        else if (n == (long long)FN * RD)         U    = (const float*)d_in[i];
    }
    float* out = (float*)d_out;

    compute_w_kernel<<<512, 256, CW_SMEM_BYTES>>>(U, R);
    score_kernel<<<512, 256>>>(conv, out);
}